// round 1
// baseline (speedup 1.0000x reference)
#include <cuda_runtime.h>

// PhotonicMesh: 512-port Clements mesh, 512 layers, 1024 batch rows.
// Strategy: precompute per-(layer,pair) coefficients (ct, st, cos(phi), sin(phi))
// into a 2MB __device__ table; main kernel keeps the full complex state of one
// row in the registers of one warp (lane t owns ports [16t, 16t+16)).
// Even layers are fully lane-local; odd layers exchange one complex value per
// lane boundary via warp shuffles. No shared memory, no barriers.

#define N_PORT  512
#define N_LAYER 512
#define N_PAIR  256
#define N_ROW   1024
// sqrt(10^(-0.2/10)) = 10^(-0.01)
#define ATTEN_F 0.97723722095581054f

// Coefficient table, layout: [(l*8 + k)*32 + lane] where pair p = 8*lane + k.
// This makes the per-k load across a warp a fully coalesced 512B read.
__device__ float4 g_coef[N_LAYER * N_PAIR];

__global__ void pm_coef_kernel(const float* __restrict__ thetas,
                               const float* __restrict__ phis,
                               const int*   __restrict__ mzi_idx) {
    int l = blockIdx.x;      // layer
    int p = threadIdx.x;     // pair index within layer
    float4 c = make_float4(1.0f, 0.0f, 1.0f, 0.0f);  // identity (unused slots)
    bool odd = (l & 1) != 0;
    bool valid = (!odd) || (p < N_PAIR - 1);         // odd layers have 255 pairs
    if (valid) {
        int i = odd ? (2 * p + 1) : (2 * p);         // upper port of the pair
        int m = mzi_idx[l * N_PORT + i];
        float st, ct, sp, cp;
        sincosf(thetas[m], &st, &ct);
        sincosf(phis[m],   &sp, &cp);
        c = make_float4(ct * ATTEN_F, st * ATTEN_F, cp, sp);
    }
    g_coef[(l * 8 + (p & 7)) * 32 + (p >> 3)] = c;
}

// new_i = ep*(ct*x_i + st*x_j) ; new_j = ct*x_j - st*x_i
__device__ __forceinline__ void butterfly(float2& xi, float2& xj, float4 c) {
    float ct = c.x, st = c.y, er = c.z, ei = c.w;
    float ur = ct * xi.x + st * xj.x;
    float ui = ct * xi.y + st * xj.y;
    float vr = ct * xj.x - st * xi.x;
    float vi = ct * xj.y - st * xi.y;
    xi.x = er * ur - ei * ui;
    xi.y = er * ui + ei * ur;
    xj.x = vr;
    xj.y = vi;
}

__global__ __launch_bounds__(128, 1)
void pm_mesh_kernel(const float* __restrict__ x, float* __restrict__ out) {
    const int lane = threadIdx.x & 31;
    const int w    = blockIdx.x * (blockDim.x >> 5) + (threadIdx.x >> 5);
    const int row0 = w * 2;   // 2 rows per warp

    float2 s[2][16];          // complex state: lane owns ports 16*lane .. 16*lane+15

    // ---- load input (real), imag = 0 ----
    const float4* x4 = reinterpret_cast<const float4*>(x);
    #pragma unroll
    for (int r = 0; r < 2; r++) {
        #pragma unroll
        for (int v = 0; v < 4; v++) {
            float4 q = x4[(size_t)(row0 + r) * (N_PORT / 4) + lane * 4 + v];
            s[r][4 * v + 0] = make_float2(q.x, 0.f);
            s[r][4 * v + 1] = make_float2(q.y, 0.f);
            s[r][4 * v + 2] = make_float2(q.z, 0.f);
            s[r][4 * v + 3] = make_float2(q.w, 0.f);
        }
    }

    // ---- propagate through 512 layers (process even+odd per iteration) ----
    for (int l = 0; l < N_LAYER; l += 2) {
        float4 c[8];

        // EVEN layer l: pairs (16*lane+2k, 16*lane+2k+1), all lane-local
        {
            const float4* cl = g_coef + (size_t)l * N_PAIR;
            #pragma unroll
            for (int k = 0; k < 8; k++) c[k] = cl[k * 32 + lane];
            #pragma unroll
            for (int r = 0; r < 2; r++) {
                #pragma unroll
                for (int k = 0; k < 8; k++)
                    butterfly(s[r][2 * k], s[r][2 * k + 1], c[k]);
            }
        }

        // ODD layer l+1: local pairs (2k+1, 2k+2) for k=0..6; cross pair
        // (16*lane+15, 16*(lane+1)) handled via shuffles; ports 0 and 511 pass.
        {
            const float4* cl = g_coef + (size_t)(l + 1) * N_PAIR;
            #pragma unroll
            for (int k = 0; k < 8; k++) c[k] = cl[k * 32 + lane];
            // coefficients of the cross pair owned by lane-1 (for our port 0)
            float ctm = __shfl_up_sync(0xffffffffu, c[7].x, 1);
            float stm = __shfl_up_sync(0xffffffffu, c[7].y, 1);
            #pragma unroll
            for (int r = 0; r < 2; r++) {
                // snapshot neighbor values BEFORE any update this layer
                float xjr = __shfl_down_sync(0xffffffffu, s[r][0].x, 1);   // (lane+1).port0
                float xji = __shfl_down_sync(0xffffffffu, s[r][0].y, 1);
                float xir = __shfl_up_sync(0xffffffffu, s[r][15].x, 1);    // (lane-1).port15
                float xii = __shfl_up_sync(0xffffffffu, s[r][15].y, 1);
                #pragma unroll
                for (int k = 0; k < 7; k++)
                    butterfly(s[r][2 * k + 1], s[r][2 * k + 2], c[k]);
                if (lane < 31) {  // upper port of cross pair: gets the phase
                    float ct = c[7].x, st = c[7].y, er = c[7].z, ei = c[7].w;
                    float ur = ct * s[r][15].x + st * xjr;
                    float ui = ct * s[r][15].y + st * xji;
                    s[r][15].x = er * ur - ei * ui;
                    s[r][15].y = er * ui + ei * ur;
                }
                if (lane > 0) {   // lower port of cross pair: real coefficients
                    float2 x0 = s[r][0];
                    s[r][0].x = ctm * x0.x - stm * xir;
                    s[r][0].y = ctm * x0.y - stm * xii;
                }
            }
        }
    }

    // ---- square-law detection + store ----
    float4* o4 = reinterpret_cast<float4*>(out);
    #pragma unroll
    for (int r = 0; r < 2; r++) {
        #pragma unroll
        for (int v = 0; v < 4; v++) {
            float4 q;
            q.x = s[r][4 * v + 0].x * s[r][4 * v + 0].x + s[r][4 * v + 0].y * s[r][4 * v + 0].y;
            q.y = s[r][4 * v + 1].x * s[r][4 * v + 1].x + s[r][4 * v + 1].y * s[r][4 * v + 1].y;
            q.z = s[r][4 * v + 2].x * s[r][4 * v + 2].x + s[r][4 * v + 2].y * s[r][4 * v + 2].y;
            q.w = s[r][4 * v + 3].x * s[r][4 * v + 3].x + s[r][4 * v + 3].y * s[r][4 * v + 3].y;
            o4[(size_t)(row0 + r) * (N_PORT / 4) + lane * 4 + v] = q;
        }
    }
}

extern "C" void kernel_launch(void* const* d_in, const int* in_sizes, int n_in,
                              void* d_out, int out_size) {
    const float* x       = (const float*)d_in[0];
    const float* thetas  = (const float*)d_in[1];
    const float* phis    = (const float*)d_in[2];
    // d_in[3] = partner (unused: structure is static)
    const int*   mzi_idx = (const int*)d_in[4];
    // d_in[5] = role (unused: structure is static)
    float* out = (float*)d_out;

    pm_coef_kernel<<<N_LAYER, N_PAIR>>>(thetas, phis, mzi_idx);
    // 512 warps total: warp w handles rows 2w, 2w+1
    pm_mesh_kernel<<<128, 128>>>(x, out);
}

// round 2
// speedup vs baseline: 1.4590x; 1.4590x over previous
#include <cuda_runtime.h>

// PhotonicMesh: 512-port Clements mesh, 512 layers, 1024 batch rows.
// R2: 1 row per warp (1024 warps = 128 CTAs x 256 threads, one full wave,
// 2 warps/SMSP) + ping-pong software pipeline on coefficient loads so the
// LDG latency of layer l+2/l+3 coefficients is hidden under compute of l/l+1.
// Lane t owns ports [16t, 16t+16) of its row; odd layers exchange one complex
// value per lane boundary via shuffles. No shared memory, no barriers.

#define N_PORT  512
#define N_LAYER 512
#define N_PAIR  256
#define N_ROW   1024
// sqrt(10^(-0.2/10)) = 10^(-0.01)
#define ATTEN_F 0.97723722095581054f

// Coefficient table, layout: [(l*8 + k)*32 + lane] where pair p = 8*lane + k.
// Per-k load across a warp is a fully coalesced 512B read.
__device__ float4 g_coef[N_LAYER * N_PAIR];

__global__ void pm_coef_kernel(const float* __restrict__ thetas,
                               const float* __restrict__ phis,
                               const int*   __restrict__ mzi_idx) {
    int l = blockIdx.x;      // layer
    int p = threadIdx.x;     // pair index within layer
    float4 c = make_float4(1.0f, 0.0f, 1.0f, 0.0f);  // identity (unused slots)
    bool odd = (l & 1) != 0;
    bool valid = (!odd) || (p < N_PAIR - 1);         // odd layers have 255 pairs
    if (valid) {
        int i = odd ? (2 * p + 1) : (2 * p);         // upper port of the pair
        int m = mzi_idx[l * N_PORT + i];
        float st, ct, sp, cp;
        sincosf(thetas[m], &st, &ct);
        sincosf(phis[m],   &sp, &cp);
        c = make_float4(ct * ATTEN_F, st * ATTEN_F, cp, sp);
    }
    g_coef[(l * 8 + (p & 7)) * 32 + (p >> 3)] = c;
}

// new_i = ep*(ct*x_i + st*x_j) ; new_j = ct*x_j - st*x_i
__device__ __forceinline__ void butterfly(float2& xi, float2& xj, float4 c) {
    float ct = c.x, st = c.y, er = c.z, ei = c.w;
    float ur = ct * xi.x + st * xj.x;
    float ui = ct * xi.y + st * xj.y;
    float vr = ct * xj.x - st * xi.x;
    float vi = ct * xj.y - st * xi.y;
    xi.x = er * ur - ei * ui;
    xi.y = er * ui + ei * ur;
    xj.x = vr;
    xj.y = vi;
}

// Load coefficients for even layer l (c[0..7]) and odd layer l+1 (c[8..15]).
__device__ __forceinline__ void load_coefs(float4* c, int l, int lane) {
    const float4* ce = g_coef + (size_t)l * N_PAIR;
    const float4* co = g_coef + (size_t)(l + 1) * N_PAIR;
    #pragma unroll
    for (int k = 0; k < 8; k++) c[k]     = __ldg(&ce[k * 32 + lane]);
    #pragma unroll
    for (int k = 0; k < 8; k++) c[k + 8] = __ldg(&co[k * 32 + lane]);
}

// EVEN layer: pairs (16*lane+2k, 16*lane+2k+1), all lane-local.
__device__ __forceinline__ void do_even(float2* s, const float4* c) {
    #pragma unroll
    for (int k = 0; k < 8; k++)
        butterfly(s[2 * k], s[2 * k + 1], c[k]);
}

// ODD layer: local pairs (2k+1, 2k+2) for k=0..6; cross pair
// (16*lane+15, 16*(lane+1)) via shuffles; ports 0 and 511 pass through.
__device__ __forceinline__ void do_odd(float2* s, const float4* c, int lane) {
    // coefficients of the cross pair owned by lane-1 (acts on our port 0)
    float ctm = __shfl_up_sync(0xffffffffu, c[7].x, 1);
    float stm = __shfl_up_sync(0xffffffffu, c[7].y, 1);
    // snapshot neighbor values BEFORE any update this layer
    float xjr = __shfl_down_sync(0xffffffffu, s[0].x, 1);   // (lane+1).port0
    float xji = __shfl_down_sync(0xffffffffu, s[0].y, 1);
    float xir = __shfl_up_sync(0xffffffffu, s[15].x, 1);    // (lane-1).port15
    float xii = __shfl_up_sync(0xffffffffu, s[15].y, 1);
    #pragma unroll
    for (int k = 0; k < 7; k++)
        butterfly(s[2 * k + 1], s[2 * k + 2], c[k]);
    if (lane < 31) {  // upper port of cross pair: gets the phase
        float ct = c[7].x, st = c[7].y, er = c[7].z, ei = c[7].w;
        float ur = ct * s[15].x + st * xjr;
        float ui = ct * s[15].y + st * xji;
        s[15].x = er * ur - ei * ui;
        s[15].y = er * ui + ei * ur;
    }
    if (lane > 0) {   // lower port of cross pair: real coefficients
        float2 x0 = s[0];
        s[0].x = ctm * x0.x - stm * xir;
        s[0].y = ctm * x0.y - stm * xii;
    }
}

__global__ __launch_bounds__(256, 1)
void pm_mesh_kernel(const float* __restrict__ x, float* __restrict__ out) {
    const int lane = threadIdx.x & 31;
    const int row  = blockIdx.x * (blockDim.x >> 5) + (threadIdx.x >> 5);

    float2 s[16];             // complex state: lane owns ports 16*lane..16*lane+15

    // ---- load input (real), imag = 0 ----
    const float4* x4 = reinterpret_cast<const float4*>(x);
    #pragma unroll
    for (int v = 0; v < 4; v++) {
        float4 q = x4[(size_t)row * (N_PORT / 4) + lane * 4 + v];
        s[4 * v + 0] = make_float2(q.x, 0.f);
        s[4 * v + 1] = make_float2(q.y, 0.f);
        s[4 * v + 2] = make_float2(q.z, 0.f);
        s[4 * v + 3] = make_float2(q.w, 0.f);
    }

    // ---- software-pipelined propagation: ping-pong coefficient buffers ----
    float4 cA[16], cB[16];
    load_coefs(cA, 0, lane);

    // Each outer iteration processes 4 layers (A then B) while prefetching.
    #pragma unroll 1
    for (int l = 0; l < N_LAYER; l += 4) {
        int ln1 = l + 2;  if (ln1 > N_LAYER - 2) ln1 = 0;   // clamp (result unused)
        load_coefs(cB, ln1, lane);
        do_even(s, cA);
        do_odd (s, cA + 8, lane);

        int ln2 = l + 4;  if (ln2 > N_LAYER - 2) ln2 = 0;   // clamp (result unused)
        load_coefs(cA, ln2, lane);
        do_even(s, cB);
        do_odd (s, cB + 8, lane);
    }

    // ---- square-law detection + store ----
    float4* o4 = reinterpret_cast<float4*>(out);
    #pragma unroll
    for (int v = 0; v < 4; v++) {
        float4 q;
        q.x = s[4 * v + 0].x * s[4 * v + 0].x + s[4 * v + 0].y * s[4 * v + 0].y;
        q.y = s[4 * v + 1].x * s[4 * v + 1].x + s[4 * v + 1].y * s[4 * v + 1].y;
        q.z = s[4 * v + 2].x * s[4 * v + 2].x + s[4 * v + 2].y * s[4 * v + 2].y;
        q.w = s[4 * v + 3].x * s[4 * v + 3].x + s[4 * v + 3].y * s[4 * v + 3].y;
        o4[(size_t)row * (N_PORT / 4) + lane * 4 + v] = q;
    }
}

extern "C" void kernel_launch(void* const* d_in, const int* in_sizes, int n_in,
                              void* d_out, int out_size) {
    const float* x       = (const float*)d_in[0];
    const float* thetas  = (const float*)d_in[1];
    const float* phis    = (const float*)d_in[2];
    // d_in[3] = partner (unused: structure is static)
    const int*   mzi_idx = (const int*)d_in[4];
    // d_in[5] = role (unused: structure is static)
    float* out = (float*)d_out;

    pm_coef_kernel<<<N_LAYER, N_PAIR>>>(thetas, phis, mzi_idx);
    // 1024 warps: warp w handles row w; 128 CTAs x 8 warps = one full wave
    pm_mesh_kernel<<<128, 256>>>(x, out);
}